// round 16
// baseline (speedup 1.0000x reference)
#include <cuda_runtime.h>
#include <cuda_bf16.h>
#include <cstdint>

#define N_NODES 100000
#define F1 128
#define F2 64
#define EMAX 1600000

// Scratch (device globals: allocation-free, graph-safe)
__device__ float g_bufA[N_NODES * F2];   // GEMM output (pre-aggregation messages)
__device__ float g_rso[N_NODES];         // rsqrt(deg_out)
__device__ float g_rsi[N_NODES];         // rsqrt(deg_in)
__device__ int   g_dego[N_NODES];
__device__ int   g_degi[N_NODES];
__device__ int   g_off[N_NODES];         // segment start per dst node
__device__ int   g_cur[N_NODES];         // fill cursor per dst node
__device__ int   g_sorted[EMAX];         // src indices grouped by dst
__device__ int   g_total;                // segment allocator

// ---------------------------------------------------------------------------
__global__ void k_zero() {
    int i = blockIdx.x * blockDim.x + threadIdx.x;
    if (i < N_NODES) { g_dego[i] = 0; g_degi[i] = 0; }
    if (i == 0) g_total = 0;
}

__global__ void k_degree(const int* __restrict__ src, const int* __restrict__ dst, int E) {
    int i = blockIdx.x * blockDim.x + threadIdx.x;
    if (i >= E) return;
    atomicAdd(&g_dego[src[i]], 1);
    atomicAdd(&g_degi[dst[i]], 1);
}

// Segment allocation (warp scan + 1 atomic/warp) fused with norm computation.
__global__ void k_alloc() {
    int i = blockIdx.x * blockDim.x + threadIdx.x;
    int lane = threadIdx.x & 31;
    int deg = 0, dego = 0;
    if (i < N_NODES) { deg = g_degi[i]; dego = g_dego[i]; }
    int incl = deg;
#pragma unroll
    for (int o = 1; o < 32; o <<= 1) {
        int n = __shfl_up_sync(0xFFFFFFFFu, incl, o);
        if (lane >= o) incl += n;
    }
    int wtotal = __shfl_sync(0xFFFFFFFFu, incl, 31);
    int base = 0;
    if (lane == 0) base = atomicAdd(&g_total, wtotal);
    base = __shfl_sync(0xFFFFFFFFu, base, 0);
    if (i < N_NODES) {
        int off = base + incl - deg;
        g_off[i] = off;
        g_cur[i] = off;
        g_rsi[i] = rsqrtf((float)max(deg, 1));
        g_rso[i] = rsqrtf((float)max(dego, 1));
    }
}

// Group src indices by dst (counting-sort placement).
__global__ void k_bin(const int* __restrict__ src, const int* __restrict__ dst, int E) {
    int e = blockIdx.x * blockDim.x + threadIdx.x;
    if (e >= E) return;
    int d = dst[e];
    int p = atomicAdd(&g_cur[d], 1);
    g_sorted[p] = src[e];
}

// ---------------------------------------------------------------------------
// Y[r, :] = X[r, :] @ W     X:[M,K] W:[K,64] Y:[M,64]
// R15's k-chunked 4x4 blocking (32 KB static smem, ~5 blocks/SM).
template <int K>
__global__ void __launch_bounds__(256)
k_gemm(const float* __restrict__ X, const float* __restrict__ W,
       float* __restrict__ Y, int M) {
    constexpr int KC = 64;
    constexpr int NCH = K / KC;
    __shared__ float sW[KC * 64];
    __shared__ float sX[64 * KC];

    const int tid = threadIdx.x;
    const int row0 = blockIdx.x * 64;
    const int tx = tid & 15;
    const int ty = tid >> 4;

    float acc[4][4];
#pragma unroll
    for (int j = 0; j < 4; j++)
#pragma unroll
        for (int c = 0; c < 4; c++) acc[j][c] = 0.0f;

#pragma unroll
    for (int ch = 0; ch < NCH; ++ch) {
        for (int i = tid; i < KC * 16; i += 256)
            ((float4*)sW)[i] = ((const float4*)(W + ch * KC * 64))[i];

        for (int i = tid; i < 64 * (KC / 4); i += 256) {
            int r = i / (KC / 4), c = i % (KC / 4);
            float4 v = make_float4(0.f, 0.f, 0.f, 0.f);
            if (row0 + r < M)
                v = ((const float4*)(X + (size_t)(row0 + r) * K + ch * KC))[c];
            ((float4*)sX)[i] = v;
        }
        __syncthreads();

        for (int k4 = 0; k4 < KC / 4; ++k4) {
            float4 xv[4];
#pragma unroll
            for (int j = 0; j < 4; j++)
                xv[j] = ((const float4*)(sX + (ty * 4 + j) * KC))[k4];
#pragma unroll
            for (int kk = 0; kk < 4; kk++) {
                float4 wv = ((const float4*)(sW + (k4 * 4 + kk) * 64))[tx];
#pragma unroll
                for (int j = 0; j < 4; j++) {
                    const float* xp = (const float*)&xv[j];
                    float xs = xp[kk];
                    acc[j][0] += xs * wv.x;
                    acc[j][1] += xs * wv.y;
                    acc[j][2] += xs * wv.z;
                    acc[j][3] += xs * wv.w;
                }
            }
        }
        __syncthreads();
    }

#pragma unroll
    for (int j = 0; j < 4; j++) {
        int gr = row0 + ty * 4 + j;
        if (gr < M) {
            float4 o = make_float4(acc[j][0], acc[j][1], acc[j][2], acc[j][3]);
            ((float4*)(Y + (size_t)gr * 64))[tx] = o;
        }
    }
}

// ---------------------------------------------------------------------------
// Fused layer-1 aggregation + layer-2 GEMM, per 64-node tile:
//   phase 1: sH[n,:] = relu( rsi[n] * sum_{s} rso[s]*A[s,:] + b1 )   (gather)
//   phase 2: Y[n,:]  = (sH[n,:] @ W2) * rso[n]                       (smem GEMM)
__global__ void __launch_bounds__(256)
k_agg_gemm(const float* __restrict__ Asrc, const float* __restrict__ b1,
           const float* __restrict__ W2, float* __restrict__ Y, int M) {
    __shared__ float sH[64 * 64];   // h1 tile (16 KB)
    __shared__ float sW[64 * 64];   // W2      (16 KB)

    const int tid = threadIdx.x;
    const int node0 = blockIdx.x * 64;

    // Load W2 [64][64]
    for (int i = tid; i < 64 * 16; i += 256)
        ((float4*)sW)[i] = ((const float4*)W2)[i];

    // Phase 1: aggregate 64 nodes (16 threads/node, 4 passes)
    const float4* A = (const float4*)Asrc;
    const int c = tid & 15;
    float4 bb = __ldg(((const float4*)b1) + c);
#pragma unroll
    for (int p = 0; p < 4; ++p) {
        int nl = p * 16 + (tid >> 4);        // node-local index 0..63
        int node = node0 + nl;
        float4 acc = make_float4(0.f, 0.f, 0.f, 0.f);
        if (node < M) {
            int base = g_off[node];
            int end  = base + g_degi[node];
            int i = base;
            for (; i + 4 <= end; i += 4) {
                int s0 = __ldg(g_sorted + i);
                int s1 = __ldg(g_sorted + i + 1);
                int s2 = __ldg(g_sorted + i + 2);
                int s3 = __ldg(g_sorted + i + 3);
                float4 v0 = __ldg(A + (size_t)s0 * 16 + c);
                float4 v1 = __ldg(A + (size_t)s1 * 16 + c);
                float4 v2 = __ldg(A + (size_t)s2 * 16 + c);
                float4 v3 = __ldg(A + (size_t)s3 * 16 + c);
                float r0 = __ldg(g_rso + s0), r1 = __ldg(g_rso + s1);
                float r2 = __ldg(g_rso + s2), r3 = __ldg(g_rso + s3);
                acc.x += (v0.x * r0 + v1.x * r1) + (v2.x * r2 + v3.x * r3);
                acc.y += (v0.y * r0 + v1.y * r1) + (v2.y * r2 + v3.y * r3);
                acc.z += (v0.z * r0 + v1.z * r1) + (v2.z * r2 + v3.z * r3);
                acc.w += (v0.w * r0 + v1.w * r1) + (v2.w * r2 + v3.w * r3);
            }
            for (; i < end; ++i) {
                int s = __ldg(g_sorted + i);
                float4 v = __ldg(A + (size_t)s * 16 + c);
                float r = __ldg(g_rso + s);
                acc.x += v.x * r; acc.y += v.y * r; acc.z += v.z * r; acc.w += v.w * r;
            }
            float sc = g_rsi[node];
            acc.x = fmaxf(acc.x * sc + bb.x, 0.f);
            acc.y = fmaxf(acc.y * sc + bb.y, 0.f);
            acc.z = fmaxf(acc.z * sc + bb.z, 0.f);
            acc.w = fmaxf(acc.w * sc + bb.w, 0.f);
        }
        *(float4*)(sH + nl * 64 + c * 4) = acc;
    }
    __syncthreads();

    // Phase 2: mini-GEMM 64x64x64 out of smem (proven 4x4 blocking)
    const int tx = tid & 15;
    const int ty = tid >> 4;
    float acc[4][4];
#pragma unroll
    for (int j = 0; j < 4; j++)
#pragma unroll
        for (int cc = 0; cc < 4; cc++) acc[j][cc] = 0.0f;

    for (int k4 = 0; k4 < 16; ++k4) {
        float4 xv[4];
#pragma unroll
        for (int j = 0; j < 4; j++)
            xv[j] = ((const float4*)(sH + (ty * 4 + j) * 64))[k4];
#pragma unroll
        for (int kk = 0; kk < 4; kk++) {
            float4 wv = ((const float4*)(sW + (k4 * 4 + kk) * 64))[tx];
#pragma unroll
            for (int j = 0; j < 4; j++) {
                const float* xp = (const float*)&xv[j];
                float xs = xp[kk];
                acc[j][0] += xs * wv.x;
                acc[j][1] += xs * wv.y;
                acc[j][2] += xs * wv.z;
                acc[j][3] += xs * wv.w;
            }
        }
    }

#pragma unroll
    for (int j = 0; j < 4; j++) {
        int gr = node0 + ty * 4 + j;
        if (gr < M) {
            float s = g_rso[gr];
            float4 o = make_float4(acc[j][0] * s, acc[j][1] * s, acc[j][2] * s, acc[j][3] * s);
            ((float4*)(Y + (size_t)gr * 64))[tx] = o;
        }
    }
}

// ---------------------------------------------------------------------------
// Final gather-aggregate (layer 2): out[n] = rsi[n] * sum A[s] + b2
__global__ void k_agg2(const float* __restrict__ Asrc, const float* __restrict__ bias,
                       float* __restrict__ out) {
    int idx = blockIdx.x * blockDim.x + threadIdx.x;
    if (idx >= N_NODES * 16) return;
    int node = idx >> 4;
    int c = idx & 15;

    int base = g_off[node];
    int deg  = g_degi[node];
    int end  = base + deg;

    const float4* A = (const float4*)Asrc;
    float4 acc = make_float4(0.f, 0.f, 0.f, 0.f);

    int i = base;
    for (; i + 4 <= end; i += 4) {
        int s0 = __ldg(g_sorted + i);
        int s1 = __ldg(g_sorted + i + 1);
        int s2 = __ldg(g_sorted + i + 2);
        int s3 = __ldg(g_sorted + i + 3);
        float4 v0 = __ldg(A + (size_t)s0 * 16 + c);
        float4 v1 = __ldg(A + (size_t)s1 * 16 + c);
        float4 v2 = __ldg(A + (size_t)s2 * 16 + c);
        float4 v3 = __ldg(A + (size_t)s3 * 16 + c);
        acc.x += (v0.x + v1.x) + (v2.x + v3.x);
        acc.y += (v0.y + v1.y) + (v2.y + v3.y);
        acc.z += (v0.z + v1.z) + (v2.z + v3.z);
        acc.w += (v0.w + v1.w) + (v2.w + v3.w);
    }
    for (; i < end; ++i) {
        int s = __ldg(g_sorted + i);
        float4 v = __ldg(A + (size_t)s * 16 + c);
        acc.x += v.x; acc.y += v.y; acc.z += v.z; acc.w += v.w;
    }

    float sc = g_rsi[node];
    float4 bb = __ldg(((const float4*)bias) + c);
    float4 o;
    o.x = acc.x * sc + bb.x;
    o.y = acc.y * sc + bb.y;
    o.z = acc.z * sc + bb.z;
    o.w = acc.w * sc + bb.w;
    ((float4*)out)[idx] = o;
}

// ---------------------------------------------------------------------------
extern "C" void kernel_launch(void* const* d_in, const int* in_sizes, int n_in,
                              void* d_out, int out_size) {
    const float* x   = (const float*)d_in[0];
    const int*   src = (const int*)  d_in[1];
    const int*   dst = (const int*)  d_in[2];
    const float* W1  = (const float*)d_in[3];
    const float* b1  = (const float*)d_in[4];
    const float* W2  = (const float*)d_in[5];
    const float* b2  = (const float*)d_in[6];
    float* out = (float*)d_out;

    const int E = in_sizes[1];
    const int M = in_sizes[0] / F1;  // == N_NODES

    void* pA = nullptr;
    cudaGetSymbolAddress(&pA, g_bufA);

    // Side stream + events for fork/join (created once on first, non-captured
    // call; no device memory involved).
    static cudaStream_t s2 = nullptr;
    static cudaEvent_t evFork = nullptr, evJoin = nullptr;
    if (!s2) {
        cudaStreamCreateWithFlags(&s2, cudaStreamNonBlocking);
        cudaEventCreateWithFlags(&evFork, cudaEventDisableTiming);
        cudaEventCreateWithFlags(&evJoin, cudaEventDisableTiming);
    }

    const int T = 256;

    // Fork: preprocessing chain (latency-bound) on s2, GEMM1 (compute-bound)
    // on the main stream. GEMM1 depends only on x/W1 (rso applied in agg1).
    cudaEventRecord(evFork, 0);
    cudaStreamWaitEvent(s2, evFork, 0);
    k_zero<<<(N_NODES + T - 1) / T, T, 0, s2>>>();
    k_degree<<<(E + T - 1) / T, T, 0, s2>>>(src, dst, E);
    k_alloc<<<(N_NODES + T - 1) / T, T, 0, s2>>>();
    k_bin<<<(E + T - 1) / T, T, 0, s2>>>(src, dst, E);
    cudaEventRecord(evJoin, s2);

    // Main stream: layer-1 GEMM (unscaled): A = x @ W1
    k_gemm<F1><<<(M + 63) / 64, 256>>>(x, W1, (float*)pA, M);

    // Join: aggregation needs both GEMM1 and the bin structure.
    cudaStreamWaitEvent(0, evJoin, 0);

    // Fused: h1 = relu(rsi * sum rso[s]*A[s] + b1); A = (h1 @ W2) * rso
    // (in-place into g_bufA is safe: each block reads only rows of A indexed by
    //  src lists during phase 1, and writes only its own 64 rows after a sync…
    //  NOT safe in-place — other blocks may still read our rows. Use out as
    //  intermediate? out is [N,64] fp32 = exactly the right size.)
    k_agg_gemm<<<(M + 63) / 64, 256>>>((const float*)pA, b1, W2, out, M);

    // out currently holds layer-2 messages; gather into g_bufA then copy?
    // Cleaner: gather directly from out into g_bufA, then final result lives
    // in g_bufA... but d_out must hold the answer. Run agg2 writing to pA is
    // wrong target. Instead: agg2 reads `out` (messages) and writes g_bufA,
    // then a copy? Avoid: use g_bufA as the k_agg_gemm destination is unsafe;
    // use `out` as messages (done above), and have agg2 read `out` while
    // writing g_bufA, then memcpy g_bufA -> out (device-to-device, graph-ok).
    k_agg2<<<(N_NODES * 16 + T - 1) / T, T>>>(out, b2, (float*)pA);
    cudaMemcpyAsync(out, pA, (size_t)N_NODES * F2 * sizeof(float),
                    cudaMemcpyDeviceToDevice, 0);
}